// round 9
// baseline (speedup 1.0000x reference)
#include <cuda_runtime.h>
#include <mma.h>
#include <math.h>

using namespace nvcuda;

#define NN 20000
#define NP 20096          // 157 * 128 (padded rows for GEMM outputs)
#define EE 320000
#define GG 128

static inline int cdiv(int a, int b) { return (a + b - 1) / b; }

// ---------------- scratch ----------------
__device__ float g_xl1[NP * 1024];
__device__ float g_xr1[NP * 1024];
__device__ float g_out1[NP * 1024];
__device__ float g_d256a[NP * 256];
__device__ float g_xr2[NP * 256];
__device__ float g_out2[NN * 256];
__device__ float g_h64[NP * 64];
__device__ float g_score[EE * 4];
__device__ int   g_deg[NN];
__device__ int   g_rowstart[NN + 1];
__device__ int   g_cursor[NN];
__device__ int   g_esrc[EE];
__device__ int   g_eid[EE];
__device__ float g_bnsum[1024];
__device__ float g_bnsq[1024];
__device__ float g_scale[1024];
__device__ float g_shift[1024];
__device__ float g_pool[GG * 256];
__device__ float g_fc1o[GG * 64];

// ---------------- CSR build ----------------
__global__ void hist_kernel(const int* __restrict__ ei, int* __restrict__ deg)
{
    int e = blockIdx.x * blockDim.x + threadIdx.x;
    if (e < EE) atomicAdd(&deg[ei[EE + e]], 1);
}

__global__ __launch_bounds__(512) void scan_kernel(const int* __restrict__ deg,
                                                   int* __restrict__ rowstart)
{
    __shared__ int ps[512];
    int t = threadIdx.x;
    const int CH = (NN + 511) / 512;
    int s0 = t * CH, s1 = min(NN, s0 + CH);
    int s = 0;
    for (int i = s0; i < s1; i++) s += deg[i];
    ps[t] = s;
    __syncthreads();
    for (int off = 1; off < 512; off <<= 1) {
        int v = (t >= off) ? ps[t - off] : 0;
        __syncthreads();
        ps[t] += v;
        __syncthreads();
    }
    int run = (t == 0) ? 0 : ps[t - 1];
    for (int i = s0; i < s1; i++) { rowstart[i] = run; run += deg[i]; }
    if (t == 511) rowstart[NN] = run;
}

__global__ void scatter_kernel(const int* __restrict__ ei, int* __restrict__ cursor,
                               int* __restrict__ esrc, int* __restrict__ eid)
{
    int e = blockIdx.x * blockDim.x + threadIdx.x;
    if (e >= EE) return;
    int dst = ei[EE + e];
    int pos = atomicAdd(&cursor[dst], 1);
    esrc[pos] = ei[e];
    eid[pos] = e;
}

// ---------------- 3xTF32 GEMM, double-buffered, hi/lo pre-split in smem -------
// C = A[M,K] @ W[K,N] (+bias, relu). BM=128, BK=32, 8 warps, 256 threads.
// a = a_hi + a_lo; acc += a_lo*b_hi + a_hi*b_lo + a_hi*b_hi  (fp32-accurate).
template <int BN, int WM, int WN, bool RELU, bool HAS_BIAS>
__global__ __launch_bounds__(256) void tf32_gemm(
    const float* __restrict__ A, const float* __restrict__ W,
    const float* __restrict__ bias, float* __restrict__ C,
    int Mld, int N, int K)
{
    constexpr int BM = 128, BK = 32;
    constexpr int AKP = BK + 4;        // 36
    constexpr int BNP = BN + 4;
    constexpr int MF = WM / 16, NF = WN / 16;
    constexpr int B_ITERS = (BK * (BN / 4)) / 256;
    constexpr int ASZ = BM * AKP;
    constexpr int BSZ = BK * BNP;

    extern __shared__ float smemf[];
    float* As_hi = smemf;                  // 2 * ASZ
    float* As_lo = As_hi + 2 * ASZ;        // 2 * ASZ
    float* Bs_hi = As_lo + 2 * ASZ;        // 2 * BSZ
    float* Bs_lo = Bs_hi + 2 * BSZ;        // 2 * BSZ
    float* biass = Bs_lo + 2 * BSZ;        // 16 * BNP

    int tid = threadIdx.x;
    int warpId = tid >> 5;
    int rowBase = blockIdx.y * BM;
    int colBase = blockIdx.x * BN;
    int wm = warpId % (BM / WM);
    int wn = warpId / (BM / WM);
    int wmBase = wm * WM;
    int wnBase = wn * WN;

    if (HAS_BIAS) {
        for (int i = tid; i < 16 * BN; i += 256) {
            int r = i / BN, c = i % BN;
            biass[r * BNP + c] = bias[colBase + c];
        }
    }

    wmma::fragment<wmma::accumulator, 16, 16, 8, float> acc[MF][NF];
#pragma unroll
    for (int i = 0; i < MF; i++)
#pragma unroll
        for (int j = 0; j < NF; j++) wmma::fill_fragment(acc[i][j], 0.f);

    float4 aPre[4];
    float4 bPre[B_ITERS];

    auto ldgTile = [&](int k0) {
#pragma unroll
        for (int it = 0; it < 4; it++) {
            int idx = tid + it * 256;
            int r = idx >> 3, c4 = idx & 7;
            int gr = rowBase + r;
            float4 v = make_float4(0.f, 0.f, 0.f, 0.f);
            if (gr < Mld) v = *reinterpret_cast<const float4*>(&A[(size_t)gr * K + k0 + c4 * 4]);
            aPre[it] = v;
        }
#pragma unroll
        for (int it = 0; it < B_ITERS; it++) {
            int idx = tid + it * 256;
            int r = idx / (BN / 4), c4 = idx % (BN / 4);
            bPre[it] = *reinterpret_cast<const float4*>(&W[(size_t)(k0 + r) * N + colBase + c4 * 4]);
        }
    };

    auto stsTile = [&](int buf) {
        float* ah = As_hi + buf * ASZ;
        float* al = As_lo + buf * ASZ;
#pragma unroll
        for (int it = 0; it < 4; it++) {
            int idx = tid + it * 256;
            int r = idx >> 3, c4 = idx & 7;
            float4 v = aPre[it];
            float4 h, l;
            h.x = wmma::__float_to_tf32(v.x); l.x = wmma::__float_to_tf32(v.x - h.x);
            h.y = wmma::__float_to_tf32(v.y); l.y = wmma::__float_to_tf32(v.y - h.y);
            h.z = wmma::__float_to_tf32(v.z); l.z = wmma::__float_to_tf32(v.z - h.z);
            h.w = wmma::__float_to_tf32(v.w); l.w = wmma::__float_to_tf32(v.w - h.w);
            *reinterpret_cast<float4*>(&ah[r * AKP + c4 * 4]) = h;
            *reinterpret_cast<float4*>(&al[r * AKP + c4 * 4]) = l;
        }
        float* bhp = Bs_hi + buf * BSZ;
        float* blp = Bs_lo + buf * BSZ;
#pragma unroll
        for (int it = 0; it < B_ITERS; it++) {
            int idx = tid + it * 256;
            int r = idx / (BN / 4), c4 = idx % (BN / 4);
            float4 v = bPre[it];
            float4 h, l;
            h.x = wmma::__float_to_tf32(v.x); l.x = wmma::__float_to_tf32(v.x - h.x);
            h.y = wmma::__float_to_tf32(v.y); l.y = wmma::__float_to_tf32(v.y - h.y);
            h.z = wmma::__float_to_tf32(v.z); l.z = wmma::__float_to_tf32(v.z - h.z);
            h.w = wmma::__float_to_tf32(v.w); l.w = wmma::__float_to_tf32(v.w - h.w);
            *reinterpret_cast<float4*>(&bhp[r * BNP + c4 * 4]) = h;
            *reinterpret_cast<float4*>(&blp[r * BNP + c4 * 4]) = l;
        }
    };

    ldgTile(0);
    stsTile(0);
    __syncthreads();

    int T = K / BK;
    for (int t = 0; t < T; t++) {
        if (t + 1 < T) ldgTile((t + 1) * BK);

        const float* Ah = As_hi + (t & 1) * ASZ;
        const float* Al = As_lo + (t & 1) * ASZ;
        const float* Bh = Bs_hi + (t & 1) * BSZ;
        const float* Bl = Bs_lo + (t & 1) * BSZ;
#pragma unroll
        for (int ks = 0; ks < BK / 8; ks++) {
            wmma::fragment<wmma::matrix_a, 16, 16, 8, wmma::precision::tf32, wmma::row_major> ah[MF], al[MF];
            wmma::fragment<wmma::matrix_b, 16, 16, 8, wmma::precision::tf32, wmma::row_major> bh[NF], bl[NF];
#pragma unroll
            for (int i = 0; i < MF; i++) {
                wmma::load_matrix_sync(ah[i], &Ah[(wmBase + i * 16) * AKP + ks * 8], AKP);
                wmma::load_matrix_sync(al[i], &Al[(wmBase + i * 16) * AKP + ks * 8], AKP);
            }
#pragma unroll
            for (int j = 0; j < NF; j++) {
                wmma::load_matrix_sync(bh[j], &Bh[(ks * 8) * BNP + wnBase + j * 16], BNP);
                wmma::load_matrix_sync(bl[j], &Bl[(ks * 8) * BNP + wnBase + j * 16], BNP);
            }
#pragma unroll
            for (int i = 0; i < MF; i++)
#pragma unroll
                for (int j = 0; j < NF; j++) {
                    wmma::mma_sync(acc[i][j], al[i], bh[j], acc[i][j]);
                    wmma::mma_sync(acc[i][j], ah[i], bl[j], acc[i][j]);
                    wmma::mma_sync(acc[i][j], ah[i], bh[j], acc[i][j]);
                }
        }

        if (t + 1 < T) stsTile((t + 1) & 1);
        __syncthreads();
    }

#pragma unroll
    for (int i = 0; i < MF; i++) {
#pragma unroll
        for (int j = 0; j < NF; j++) {
            if (HAS_BIAS) {
                wmma::fragment<wmma::accumulator, 16, 16, 8, float> bfr;
                wmma::load_matrix_sync(bfr, &biass[wnBase + j * 16], BNP, wmma::mem_row_major);
#pragma unroll
                for (int t = 0; t < acc[i][j].num_elements; t++) {
                    float v = acc[i][j].x[t] + bfr.x[t];
                    acc[i][j].x[t] = RELU ? fmaxf(v, 0.f) : v;
                }
            } else if (RELU) {
#pragma unroll
                for (int t = 0; t < acc[i][j].num_elements; t++)
                    acc[i][j].x[t] = fmaxf(acc[i][j].x[t], 0.f);
            }
            wmma::store_matrix_sync(
                &C[(size_t)(rowBase + wmBase + i * 16) * N + colBase + wnBase + j * 16],
                acc[i][j], N, wmma::mem_row_major);
        }
    }
}

// host-side smem size for tf32_gemm instantiation
static inline int gemm_smem_bytes(int BN) {
    int ASZ = 128 * 36, BSZ = 32 * (BN + 4);
    return (2 * ASZ * 2 + 2 * BSZ * 2 + 16 * (BN + 4)) * 4;
}

// ---------------- fused GATv2 edge phase (per-dst CSR, no atomics) ----------------
template <int CT, int HSHIFT>
__global__ __launch_bounds__(256) void gat_edge_kernel(
    const float* __restrict__ xl, const float* __restrict__ xr,
    const float* __restrict__ ea, const float* __restrict__ we,
    const float* __restrict__ att,
    const int* __restrict__ rowstart, const int* __restrict__ esrc,
    const int* __restrict__ eid,
    float* __restrict__ gscore_fb,
    float* __restrict__ out)
{
    constexpr int MAXDEG = 256;
    constexpr int CU = CT / 256;
    __shared__ float we_s[8 * CT];
    __shared__ float att_s[CT];
    __shared__ float xr_s[CT];
    __shared__ float sc_s[MAXDEG * 4];
    int tid = threadIdx.x, lane = tid & 31, wid = tid >> 5;
    for (int i = tid; i < 8 * CT; i += 256) we_s[i] = we[i];
    for (int i = tid; i < CT; i += 256) att_s[i] = att[i];
    __syncthreads();

    for (int node = blockIdx.x; node < NN; node += gridDim.x) {
        int rs = rowstart[node];
        int deg = rowstart[node + 1] - rs;
        if (deg == 0) {
#pragma unroll
            for (int u = 0; u < CU; u++) out[(size_t)node * CT + u * 256 + tid] = 0.f;
            continue;
        }
#pragma unroll
        for (int u = 0; u < CU; u++)
            xr_s[u * 256 + tid] = xr[(size_t)node * CT + u * 256 + tid];
        __syncthreads();
        float* sc = (deg <= MAXDEG) ? sc_s : (gscore_fb + (size_t)rs * 4);

        for (int j = wid; j < deg; j += 8) {
            int src = esrc[rs + j];
            int e = eid[rs + j];
            float eav[8];
#pragma unroll
            for (int k = 0; k < 8; k++) eav[k] = __ldg(&ea[(size_t)e * 8 + k]);
            const float* xls = xl + (size_t)src * CT;
            float acc[4] = {0.f, 0.f, 0.f, 0.f};
#pragma unroll
            for (int it = 0; it < CT / 32; it++) {
                int c = lane + 32 * it;
                const int h = (32 * it) >> HSHIFT;
                float eec = 0.f;
#pragma unroll
                for (int k = 0; k < 8; k++) eec = fmaf(eav[k], we_s[k * CT + c], eec);
                float m = xls[c] + xr_s[c] + eec;
                m = (m > 0.f) ? m : 0.2f * m;
                acc[h] = fmaf(m, att_s[c], acc[h]);
            }
#pragma unroll
            for (int h = 0; h < 4; h++) {
#pragma unroll
                for (int off = 16; off > 0; off >>= 1)
                    acc[h] += __shfl_xor_sync(0xffffffffu, acc[h], off);
            }
            if (lane == 0) {
                sc[j * 4 + 0] = acc[0];
                sc[j * 4 + 1] = acc[1];
                sc[j * 4 + 2] = acc[2];
                sc[j * 4 + 3] = acc[3];
            }
        }
        __syncthreads();

        if (wid < 4) {
            float mx = -1e30f;
            for (int j = lane; j < deg; j += 32) mx = fmaxf(mx, sc[j * 4 + wid]);
#pragma unroll
            for (int off = 16; off > 0; off >>= 1)
                mx = fmaxf(mx, __shfl_xor_sync(0xffffffffu, mx, off));
            float sum = 0.f;
            for (int j = lane; j < deg; j += 32) {
                float v = expf(sc[j * 4 + wid] - mx);
                sc[j * 4 + wid] = v;
                sum += v;
            }
#pragma unroll
            for (int off = 16; off > 0; off >>= 1)
                sum += __shfl_xor_sync(0xffffffffu, sum, off);
            float inv = 1.f / sum;
            for (int j = lane; j < deg; j += 32) sc[j * 4 + wid] *= inv;
        }
        __syncthreads();

        float racc[CU];
#pragma unroll
        for (int u = 0; u < CU; u++) racc[u] = 0.f;
        for (int j = 0; j < deg; j++) {
            int src = esrc[rs + j];
            const float* xls = xl + (size_t)src * CT;
#pragma unroll
            for (int u = 0; u < CU; u++) {
                int c = u * 256 + tid;
                float al = sc[j * 4 + (c >> HSHIFT)];
                racc[u] = fmaf(al, xls[c], racc[u]);
            }
        }
#pragma unroll
        for (int u = 0; u < CU; u++)
            out[(size_t)node * CT + u * 256 + tid] = racc[u];
        __syncthreads();
    }
}

// ---------------- BN (fused bias + relu) ----------------
template <int C>
__global__ void bn_stats_kernel(const float* __restrict__ h,
                                const float* __restrict__ bias,
                                float* __restrict__ sum, float* __restrict__ sq)
{
    int c = blockIdx.y * blockDim.x + threadIdx.x;
    int r0 = blockIdx.x * 128;
    int r1 = min(NN, r0 + 128);
    float b = bias[c];
    float s = 0.f, q = 0.f;
    for (int r = r0; r < r1; r++) {
        float v = h[(size_t)r * C + c] + b;
        v = fmaxf(v, 0.f);
        s += v;
        q += v * v;
    }
    atomicAdd(&sum[c], s);
    atomicAdd(&sq[c], q);
}

__global__ void bn_final_kernel(const float* __restrict__ sum, const float* __restrict__ sq,
                                const float* __restrict__ g, const float* __restrict__ b,
                                float* __restrict__ scale, float* __restrict__ shift, int C)
{
    int c = blockIdx.x * blockDim.x + threadIdx.x;
    if (c >= C) return;
    const float invN = 1.f / (float)NN;
    float mu = sum[c] * invN;
    float var = sq[c] * invN - mu * mu;
    var = fmaxf(var, 0.f);
    float rs = rsqrtf(var + 1e-5f);
    float sc = g[c] * rs;
    scale[c] = sc;
    shift[c] = b[c] - mu * sc;
}

template <int C>
__global__ void bn_apply_kernel(float* __restrict__ h, const float* __restrict__ bias,
                                const float* __restrict__ scale, const float* __restrict__ shift)
{
    size_t i4 = (size_t)blockIdx.x * blockDim.x + threadIdx.x;
    size_t total4 = (size_t)NN * C / 4;
    if (i4 >= total4) return;
    int c = (int)((i4 * 4) % C);
    float4 v = *reinterpret_cast<float4*>(&h[i4 * 4]);
    float4 bi = *reinterpret_cast<const float4*>(&bias[c]);
    float4 sc = *reinterpret_cast<const float4*>(&scale[c]);
    float4 sh = *reinterpret_cast<const float4*>(&shift[c]);
    v.x = fmaxf(v.x + bi.x, 0.f) * sc.x + sh.x;
    v.y = fmaxf(v.y + bi.y, 0.f) * sc.y + sh.y;
    v.z = fmaxf(v.z + bi.z, 0.f) * sc.z + sh.z;
    v.w = fmaxf(v.w + bi.w, 0.f) * sc.w + sh.w;
    *reinterpret_cast<float4*>(&h[i4 * 4]) = v;
}

// ---------------- pooling (batch sorted: run-length accumulate) ------------
__global__ __launch_bounds__(256) void pool_kernel(const float* __restrict__ h,
                                                   const int* __restrict__ batch,
                                                   float* __restrict__ pooled)
{
    int c = threadIdx.x;
    int n0 = blockIdx.x * 128, n1 = min(NN, n0 + 128);
    if (n0 >= NN) return;
    float acc = 0.f;
    int cur = batch[n0];
    for (int n = n0; n < n1; n++) {
        int b = batch[n];
        if (b != cur) {
            atomicAdd(&pooled[cur * 256 + c], acc);
            acc = 0.f;
            cur = b;
        }
        acc += h[(size_t)n * 256 + c];
    }
    atomicAdd(&pooled[cur * 256 + c], acc);
}

__global__ void fc1_kernel(const float* __restrict__ pooled, const float* __restrict__ w,
                           const float* __restrict__ b, float* __restrict__ out)
{
    int gph = blockIdx.x;
    int j = threadIdx.x;
    float s = b[j];
    const float* p = pooled + gph * 256;
#pragma unroll 8
    for (int k = 0; k < 256; k++) s += p[k] * w[k * 64 + j];
    out[gph * 64 + j] = fmaxf(s, 0.f);
}

__global__ void fc2_kernel(const float* __restrict__ fc1o, const float* __restrict__ w,
                           const float* __restrict__ b, float* __restrict__ out)
{
    int gph = blockIdx.x * blockDim.x + threadIdx.x;
    if (gph >= GG) return;
    float s = b[0];
    const float* f = fc1o + gph * 64;
#pragma unroll
    for (int j = 0; j < 64; j++) s += f[j] * w[j];
    out[gph] = s;
}

// ---------------- launch ----------------
extern "C" void kernel_launch(void* const* d_in, const int* in_sizes, int n_in,
                              void* d_out, int out_size)
{
    const float* x = (const float*)d_in[0];
    const float* edge_attr = (const float*)d_in[1];
    const int* edge_index;
    const int* batch;
    int wi;
    if (in_sizes[2] == 2 * EE) {
        edge_index = (const int*)d_in[2];
        batch = (const int*)d_in[3];
        wi = 4;
    } else {
        edge_index = (const int*)d_in[n_in - 2];
        batch = (const int*)d_in[n_in - 1];
        wi = 2;
    }
    const float* dr1_w = (const float*)d_in[wi + 0];
    const float* dr1_b = (const float*)d_in[wi + 1];
    const float* dr2_w = (const float*)d_in[wi + 2];
    const float* dr2_b = (const float*)d_in[wi + 3];
    const float* c1_wl = (const float*)d_in[wi + 4];
    const float* c1_wr = (const float*)d_in[wi + 5];
    const float* c1_we = (const float*)d_in[wi + 6];
    const float* c1_att = (const float*)d_in[wi + 7];
    const float* c1_b = (const float*)d_in[wi + 8];
    const float* bn1_g = (const float*)d_in[wi + 9];
    const float* bn1_b = (const float*)d_in[wi + 10];
    const float* c2_wl = (const float*)d_in[wi + 11];
    const float* c2_wr = (const float*)d_in[wi + 12];
    const float* c2_we = (const float*)d_in[wi + 13];
    const float* c2_att = (const float*)d_in[wi + 14];
    const float* c2_b = (const float*)d_in[wi + 15];
    const float* bn2_g = (const float*)d_in[wi + 16];
    const float* bn2_b = (const float*)d_in[wi + 17];
    const float* fc1_w = (const float*)d_in[wi + 18];
    const float* fc1_b = (const float*)d_in[wi + 19];
    const float* fc2_w = (const float*)d_in[wi + 20];
    const float* fc2_b = (const float*)d_in[wi + 21];
    float* out = (float*)d_out;

    float *xl1, *xr1, *out1, *d256a, *xr2, *out2, *h64, *score;
    float *bnsum, *bnsq, *scalep, *shiftp, *pool, *fc1o;
    int *deg, *rowstart, *cursor, *esrc, *eid;
    cudaGetSymbolAddress((void**)&xl1, g_xl1);
    cudaGetSymbolAddress((void**)&xr1, g_xr1);
    cudaGetSymbolAddress((void**)&out1, g_out1);
    cudaGetSymbolAddress((void**)&d256a, g_d256a);
    cudaGetSymbolAddress((void**)&xr2, g_xr2);
    cudaGetSymbolAddress((void**)&out2, g_out2);
    cudaGetSymbolAddress((void**)&h64, g_h64);
    cudaGetSymbolAddress((void**)&score, g_score);
    cudaGetSymbolAddress((void**)&deg, g_deg);
    cudaGetSymbolAddress((void**)&rowstart, g_rowstart);
    cudaGetSymbolAddress((void**)&cursor, g_cursor);
    cudaGetSymbolAddress((void**)&esrc, g_esrc);
    cudaGetSymbolAddress((void**)&eid, g_eid);
    cudaGetSymbolAddress((void**)&bnsum, g_bnsum);
    cudaGetSymbolAddress((void**)&bnsq, g_bnsq);
    cudaGetSymbolAddress((void**)&scalep, g_scale);
    cudaGetSymbolAddress((void**)&shiftp, g_shift);
    cudaGetSymbolAddress((void**)&pool, g_pool);
    cudaGetSymbolAddress((void**)&fc1o, g_fc1o);

    dim3 blk256(256);
    const int GY = NP / 128;   // 157
    const int SM128 = gemm_smem_bytes(128);
    const int SM64 = gemm_smem_bytes(64);

    cudaFuncSetAttribute(tf32_gemm<128, 64, 32, true, true>,
                         cudaFuncAttributeMaxDynamicSharedMemorySize, SM128);
    cudaFuncSetAttribute(tf32_gemm<64, 32, 32, false, true>,
                         cudaFuncAttributeMaxDynamicSharedMemorySize, SM64);
    cudaFuncSetAttribute(tf32_gemm<128, 64, 32, false, false>,
                         cudaFuncAttributeMaxDynamicSharedMemorySize, SM128);

    // CSR build (dst-sorted)
    cudaMemsetAsync(deg, 0, NN * sizeof(int), 0);
    hist_kernel<<<cdiv(EE, 256), blk256>>>(edge_index, deg);
    scan_kernel<<<1, 512>>>(deg, rowstart);
    cudaMemcpyAsync(cursor, rowstart, NN * sizeof(int), cudaMemcpyDeviceToDevice, 0);
    scatter_kernel<<<cdiv(EE, 256), blk256>>>(edge_index, cursor, esrc, eid);

    // node MLP (pipelined 3xTF32 tensor cores, fp32-accurate)
    tf32_gemm<128, 64, 32, true, true><<<dim3(2, GY), blk256, SM128>>>(
        x, dr1_w, dr1_b, d256a, NN, 256, 512);
    tf32_gemm<64, 32, 32, false, true><<<dim3(1, GY), blk256, SM64>>>(
        d256a, dr2_w, dr2_b, h64, NP, 64, 256);
    tf32_gemm<128, 64, 32, false, false><<<dim3(8, GY), blk256, SM128>>>(
        h64, c1_wl, nullptr, xl1, NP, 1024, 64);
    tf32_gemm<128, 64, 32, false, false><<<dim3(8, GY), blk256, SM128>>>(
        h64, c1_wr, nullptr, xr1, NP, 1024, 64);

    // conv1 edge phase
    gat_edge_kernel<1024, 8><<<740, blk256>>>(xl1, xr1, edge_attr, c1_we, c1_att,
                                              rowstart, esrc, eid, score, out1);

    // bn1
    cudaMemsetAsync(bnsum, 0, 1024 * sizeof(float), 0);
    cudaMemsetAsync(bnsq, 0, 1024 * sizeof(float), 0);
    bn_stats_kernel<1024><<<dim3(cdiv(NN, 128), 4), blk256>>>(out1, c1_b, bnsum, bnsq);
    bn_final_kernel<<<4, blk256>>>(bnsum, bnsq, bn1_g, bn1_b, scalep, shiftp, 1024);
    bn_apply_kernel<1024><<<cdiv(NN * 1024 / 4, 256), blk256>>>(out1, c1_b, scalep, shiftp);

    // conv2 projections
    tf32_gemm<128, 64, 32, false, false><<<dim3(2, GY), blk256, SM128>>>(
        out1, c2_wl, nullptr, d256a, NP, 256, 1024);
    tf32_gemm<128, 64, 32, false, false><<<dim3(2, GY), blk256, SM128>>>(
        out1, c2_wr, nullptr, xr2, NP, 256, 1024);

    // conv2 edge phase
    gat_edge_kernel<256, 6><<<1184, blk256>>>(d256a, xr2, edge_attr, c2_we, c2_att,
                                              rowstart, esrc, eid, score, out2);

    // bn2
    cudaMemsetAsync(bnsum, 0, 256 * sizeof(float), 0);
    cudaMemsetAsync(bnsq, 0, 256 * sizeof(float), 0);
    bn_stats_kernel<256><<<dim3(cdiv(NN, 128), 1), blk256>>>(out2, c2_b, bnsum, bnsq);
    bn_final_kernel<<<1, blk256>>>(bnsum, bnsq, bn2_g, bn2_b, scalep, shiftp, 256);
    bn_apply_kernel<256><<<cdiv(NN * 256 / 4, 256), blk256>>>(out2, c2_b, scalep, shiftp);

    // pool + head
    cudaMemsetAsync(pool, 0, GG * 256 * sizeof(float), 0);
    pool_kernel<<<cdiv(NN, 128), blk256>>>(out2, batch, pool);
    fc1_kernel<<<GG, 64>>>(pool, fc1_w, fc1_b, fc1o);
    fc2_kernel<<<1, 128>>>(fc1o, fc2_w, fc2_b, out);
    (void)out_size; (void)n_in; (void)in_sizes;
}

// round 10
// speedup vs baseline: 1.0893x; 1.0893x over previous
#include <cuda_runtime.h>
#include <mma.h>
#include <math.h>

using namespace nvcuda;

#define NN 20000
#define NP 20096          // 157 * 128 (padded rows for GEMM outputs)
#define EE 320000
#define GG 128

static inline int cdiv(int a, int b) { return (a + b - 1) / b; }

// ---------------- scratch ----------------
__device__ float g_xl1[NP * 1024];
__device__ float g_xr1[NP * 1024];
__device__ float g_out1[NP * 1024];
__device__ float g_d256a[NP * 256];
__device__ float g_xr2[NP * 256];
__device__ float g_out2[NN * 256];
__device__ float g_h64[NP * 64];
__device__ float g_score[EE * 4];
__device__ int   g_deg[NN];
__device__ int   g_rowstart[NN + 1];
__device__ int   g_cursor[NN];
__device__ int   g_esrc[EE];
__device__ int   g_eid[EE];
__device__ float g_bnsum[1024];
__device__ float g_bnsq[1024];
__device__ float g_scale[1024];
__device__ float g_shift[1024];
__device__ float g_pool[GG * 256];
__device__ float g_fc1o[GG * 64];

// ---------------- CSR build ----------------
__global__ void hist_kernel(const int* __restrict__ ei, int* __restrict__ deg)
{
    int e = blockIdx.x * blockDim.x + threadIdx.x;
    if (e < EE) atomicAdd(&deg[ei[EE + e]], 1);
}

__global__ __launch_bounds__(512) void scan_kernel(const int* __restrict__ deg,
                                                   int* __restrict__ rowstart)
{
    __shared__ int ps[512];
    int t = threadIdx.x;
    const int CH = (NN + 511) / 512;
    int s0 = t * CH, s1 = min(NN, s0 + CH);
    int s = 0;
    for (int i = s0; i < s1; i++) s += deg[i];
    ps[t] = s;
    __syncthreads();
    for (int off = 1; off < 512; off <<= 1) {
        int v = (t >= off) ? ps[t - off] : 0;
        __syncthreads();
        ps[t] += v;
        __syncthreads();
    }
    int run = (t == 0) ? 0 : ps[t - 1];
    for (int i = s0; i < s1; i++) { rowstart[i] = run; run += deg[i]; }
    if (t == 511) rowstart[NN] = run;
}

__global__ void scatter_kernel(const int* __restrict__ ei, int* __restrict__ cursor,
                               int* __restrict__ esrc, int* __restrict__ eid)
{
    int e = blockIdx.x * blockDim.x + threadIdx.x;
    if (e >= EE) return;
    int dst = ei[EE + e];
    int pos = atomicAdd(&cursor[dst], 1);
    esrc[pos] = ei[e];
    eid[pos] = e;
}

// ---------------- 3xTF32 GEMM v3: small warp tiles, 2 CTAs/SM -----------------
// C = A[M,K] @ W[K,N] (+bias, relu). BM=128, BN=64, BK=32, 8 warps (4x2),
// warp tile 32x32. hi/lo pre-split at STS; single smem buffer; occupancy-driven
// latency hiding (2 CTAs/SM via __launch_bounds__(256,2) + 58.6KB smem).
template <bool RELU, bool HAS_BIAS>
__global__ __launch_bounds__(256, 2) void tf32_gemm(
    const float* __restrict__ A, const float* __restrict__ W,
    const float* __restrict__ bias, float* __restrict__ C,
    int Mld, int N, int K)
{
    constexpr int BM = 128, BN = 64, BK = 32;
    constexpr int AKP = BK + 4;        // 36
    constexpr int BNP = BN + 4;        // 68
    constexpr int MF = 2, NF = 2;      // warp tile 32x32
    constexpr int ASZ = BM * AKP;      // 4608
    constexpr int BSZ = BK * BNP;      // 2176

    extern __shared__ float smemf[];
    float* As_hi = smemf;              // ASZ
    float* As_lo = As_hi + ASZ;        // ASZ
    float* Bs_hi = As_lo + ASZ;        // BSZ
    float* Bs_lo = Bs_hi + BSZ;        // BSZ
    float* biass = Bs_lo + BSZ;        // 16 * BNP

    int tid = threadIdx.x;
    int warpId = tid >> 5;
    int rowBase = blockIdx.y * BM;
    int colBase = blockIdx.x * BN;
    int wmBase = (warpId & 3) * 32;    // 4 row groups
    int wnBase = (warpId >> 2) * 32;   // 2 col groups

    if (HAS_BIAS) {
        for (int i = tid; i < 16 * BN; i += 256) {
            int r = i / BN, c = i % BN;
            biass[r * BNP + c] = bias[colBase + c];
        }
    }

    wmma::fragment<wmma::accumulator, 16, 16, 8, float> acc[MF][NF];
#pragma unroll
    for (int i = 0; i < MF; i++)
#pragma unroll
        for (int j = 0; j < NF; j++) wmma::fill_fragment(acc[i][j], 0.f);

    for (int k0 = 0; k0 < K; k0 += BK) {
        // A tile: 128x32 = 1024 float4, 4 iters
#pragma unroll
        for (int it = 0; it < 4; it++) {
            int idx = tid + it * 256;
            int r = idx >> 3, c4 = idx & 7;
            int gr = rowBase + r;
            float4 v = make_float4(0.f, 0.f, 0.f, 0.f);
            if (gr < Mld) v = *reinterpret_cast<const float4*>(&A[(size_t)gr * K + k0 + c4 * 4]);
            float4 h, l;
            h.x = wmma::__float_to_tf32(v.x); l.x = wmma::__float_to_tf32(v.x - h.x);
            h.y = wmma::__float_to_tf32(v.y); l.y = wmma::__float_to_tf32(v.y - h.y);
            h.z = wmma::__float_to_tf32(v.z); l.z = wmma::__float_to_tf32(v.z - h.z);
            h.w = wmma::__float_to_tf32(v.w); l.w = wmma::__float_to_tf32(v.w - h.w);
            *reinterpret_cast<float4*>(&As_hi[r * AKP + c4 * 4]) = h;
            *reinterpret_cast<float4*>(&As_lo[r * AKP + c4 * 4]) = l;
        }
        // B tile: 32x64 = 512 float4, 2 iters
#pragma unroll
        for (int it = 0; it < 2; it++) {
            int idx = tid + it * 256;
            int r = idx >> 4, c4 = idx & 15;
            float4 v = *reinterpret_cast<const float4*>(&W[(size_t)(k0 + r) * N + colBase + c4 * 4]);
            float4 h, l;
            h.x = wmma::__float_to_tf32(v.x); l.x = wmma::__float_to_tf32(v.x - h.x);
            h.y = wmma::__float_to_tf32(v.y); l.y = wmma::__float_to_tf32(v.y - h.y);
            h.z = wmma::__float_to_tf32(v.z); l.z = wmma::__float_to_tf32(v.z - h.z);
            h.w = wmma::__float_to_tf32(v.w); l.w = wmma::__float_to_tf32(v.w - h.w);
            *reinterpret_cast<float4*>(&Bs_hi[r * BNP + c4 * 4]) = h;
            *reinterpret_cast<float4*>(&Bs_lo[r * BNP + c4 * 4]) = l;
        }
        __syncthreads();
#pragma unroll
        for (int ks = 0; ks < BK / 8; ks++) {
            wmma::fragment<wmma::matrix_a, 16, 16, 8, wmma::precision::tf32, wmma::row_major> ah[MF], al[MF];
            wmma::fragment<wmma::matrix_b, 16, 16, 8, wmma::precision::tf32, wmma::row_major> bh[NF], bl[NF];
#pragma unroll
            for (int i = 0; i < MF; i++) {
                wmma::load_matrix_sync(ah[i], &As_hi[(wmBase + i * 16) * AKP + ks * 8], AKP);
                wmma::load_matrix_sync(al[i], &As_lo[(wmBase + i * 16) * AKP + ks * 8], AKP);
            }
#pragma unroll
            for (int j = 0; j < NF; j++) {
                wmma::load_matrix_sync(bh[j], &Bs_hi[(ks * 8) * BNP + wnBase + j * 16], BNP);
                wmma::load_matrix_sync(bl[j], &Bs_lo[(ks * 8) * BNP + wnBase + j * 16], BNP);
            }
#pragma unroll
            for (int i = 0; i < MF; i++)
#pragma unroll
                for (int j = 0; j < NF; j++) {
                    wmma::mma_sync(acc[i][j], al[i], bh[j], acc[i][j]);
                    wmma::mma_sync(acc[i][j], ah[i], bl[j], acc[i][j]);
                    wmma::mma_sync(acc[i][j], ah[i], bh[j], acc[i][j]);
                }
        }
        __syncthreads();
    }

#pragma unroll
    for (int i = 0; i < MF; i++) {
#pragma unroll
        for (int j = 0; j < NF; j++) {
            if (HAS_BIAS) {
                wmma::fragment<wmma::accumulator, 16, 16, 8, float> bfr;
                wmma::load_matrix_sync(bfr, &biass[wnBase + j * 16], BNP, wmma::mem_row_major);
#pragma unroll
                for (int t = 0; t < acc[i][j].num_elements; t++) {
                    float v = acc[i][j].x[t] + bfr.x[t];
                    acc[i][j].x[t] = RELU ? fmaxf(v, 0.f) : v;
                }
            } else if (RELU) {
#pragma unroll
                for (int t = 0; t < acc[i][j].num_elements; t++)
                    acc[i][j].x[t] = fmaxf(acc[i][j].x[t], 0.f);
            }
            wmma::store_matrix_sync(
                &C[(size_t)(rowBase + wmBase + i * 16) * N + colBase + wnBase + j * 16],
                acc[i][j], N, wmma::mem_row_major);
        }
    }
}

static inline int gemm_smem_bytes() {
    return (2 * 128 * 36 + 2 * 32 * 68 + 16 * 68) * 4;   // 58,624 B
}

// ---------------- fused GATv2 edge phase (per-dst CSR, no atomics) ----------------
template <int CT, int HSHIFT>
__global__ __launch_bounds__(256) void gat_edge_kernel(
    const float* __restrict__ xl, const float* __restrict__ xr,
    const float* __restrict__ ea, const float* __restrict__ we,
    const float* __restrict__ att,
    const int* __restrict__ rowstart, const int* __restrict__ esrc,
    const int* __restrict__ eid,
    float* __restrict__ gscore_fb,
    float* __restrict__ out)
{
    constexpr int MAXDEG = 256;
    constexpr int CU = CT / 256;
    __shared__ float we_s[8 * CT];
    __shared__ float att_s[CT];
    __shared__ float xr_s[CT];
    __shared__ float sc_s[MAXDEG * 4];
    int tid = threadIdx.x, lane = tid & 31, wid = tid >> 5;
    for (int i = tid; i < 8 * CT; i += 256) we_s[i] = we[i];
    for (int i = tid; i < CT; i += 256) att_s[i] = att[i];
    __syncthreads();

    for (int node = blockIdx.x; node < NN; node += gridDim.x) {
        int rs = rowstart[node];
        int deg = rowstart[node + 1] - rs;
        if (deg == 0) {
#pragma unroll
            for (int u = 0; u < CU; u++) out[(size_t)node * CT + u * 256 + tid] = 0.f;
            continue;
        }
#pragma unroll
        for (int u = 0; u < CU; u++)
            xr_s[u * 256 + tid] = xr[(size_t)node * CT + u * 256 + tid];
        __syncthreads();
        float* sc = (deg <= MAXDEG) ? sc_s : (gscore_fb + (size_t)rs * 4);

        for (int j = wid; j < deg; j += 8) {
            int src = esrc[rs + j];
            int e = eid[rs + j];
            float eav[8];
#pragma unroll
            for (int k = 0; k < 8; k++) eav[k] = __ldg(&ea[(size_t)e * 8 + k]);
            const float* xls = xl + (size_t)src * CT;
            float acc[4] = {0.f, 0.f, 0.f, 0.f};
#pragma unroll
            for (int it = 0; it < CT / 32; it++) {
                int c = lane + 32 * it;
                const int h = (32 * it) >> HSHIFT;
                float eec = 0.f;
#pragma unroll
                for (int k = 0; k < 8; k++) eec = fmaf(eav[k], we_s[k * CT + c], eec);
                float m = xls[c] + xr_s[c] + eec;
                m = (m > 0.f) ? m : 0.2f * m;
                acc[h] = fmaf(m, att_s[c], acc[h]);
            }
#pragma unroll
            for (int h = 0; h < 4; h++) {
#pragma unroll
                for (int off = 16; off > 0; off >>= 1)
                    acc[h] += __shfl_xor_sync(0xffffffffu, acc[h], off);
            }
            if (lane == 0) {
                sc[j * 4 + 0] = acc[0];
                sc[j * 4 + 1] = acc[1];
                sc[j * 4 + 2] = acc[2];
                sc[j * 4 + 3] = acc[3];
            }
        }
        __syncthreads();

        if (wid < 4) {
            float mx = -1e30f;
            for (int j = lane; j < deg; j += 32) mx = fmaxf(mx, sc[j * 4 + wid]);
#pragma unroll
            for (int off = 16; off > 0; off >>= 1)
                mx = fmaxf(mx, __shfl_xor_sync(0xffffffffu, mx, off));
            float sum = 0.f;
            for (int j = lane; j < deg; j += 32) {
                float v = expf(sc[j * 4 + wid] - mx);
                sc[j * 4 + wid] = v;
                sum += v;
            }
#pragma unroll
            for (int off = 16; off > 0; off >>= 1)
                sum += __shfl_xor_sync(0xffffffffu, sum, off);
            float inv = 1.f / sum;
            for (int j = lane; j < deg; j += 32) sc[j * 4 + wid] *= inv;
        }
        __syncthreads();

        float racc[CU];
#pragma unroll
        for (int u = 0; u < CU; u++) racc[u] = 0.f;
        for (int j = 0; j < deg; j++) {
            int src = esrc[rs + j];
            const float* xls = xl + (size_t)src * CT;
#pragma unroll
            for (int u = 0; u < CU; u++) {
                int c = u * 256 + tid;
                float al = sc[j * 4 + (c >> HSHIFT)];
                racc[u] = fmaf(al, xls[c], racc[u]);
            }
        }
#pragma unroll
        for (int u = 0; u < CU; u++)
            out[(size_t)node * CT + u * 256 + tid] = racc[u];
        __syncthreads();
    }
}

// ---------------- BN (fused bias + relu) ----------------
template <int C>
__global__ void bn_stats_kernel(const float* __restrict__ h,
                                const float* __restrict__ bias,
                                float* __restrict__ sum, float* __restrict__ sq)
{
    int c = blockIdx.y * blockDim.x + threadIdx.x;
    int r0 = blockIdx.x * 128;
    int r1 = min(NN, r0 + 128);
    float b = bias[c];
    float s = 0.f, q = 0.f;
    for (int r = r0; r < r1; r++) {
        float v = h[(size_t)r * C + c] + b;
        v = fmaxf(v, 0.f);
        s += v;
        q += v * v;
    }
    atomicAdd(&sum[c], s);
    atomicAdd(&sq[c], q);
}

__global__ void bn_final_kernel(const float* __restrict__ sum, const float* __restrict__ sq,
                                const float* __restrict__ g, const float* __restrict__ b,
                                float* __restrict__ scale, float* __restrict__ shift, int C)
{
    int c = blockIdx.x * blockDim.x + threadIdx.x;
    if (c >= C) return;
    const float invN = 1.f / (float)NN;
    float mu = sum[c] * invN;
    float var = sq[c] * invN - mu * mu;
    var = fmaxf(var, 0.f);
    float rs = rsqrtf(var + 1e-5f);
    float sc = g[c] * rs;
    scale[c] = sc;
    shift[c] = b[c] - mu * sc;
}

template <int C>
__global__ void bn_apply_kernel(float* __restrict__ h, const float* __restrict__ bias,
                                const float* __restrict__ scale, const float* __restrict__ shift)
{
    size_t i4 = (size_t)blockIdx.x * blockDim.x + threadIdx.x;
    size_t total4 = (size_t)NN * C / 4;
    if (i4 >= total4) return;
    int c = (int)((i4 * 4) % C);
    float4 v = *reinterpret_cast<float4*>(&h[i4 * 4]);
    float4 bi = *reinterpret_cast<const float4*>(&bias[c]);
    float4 sc = *reinterpret_cast<const float4*>(&scale[c]);
    float4 sh = *reinterpret_cast<const float4*>(&shift[c]);
    v.x = fmaxf(v.x + bi.x, 0.f) * sc.x + sh.x;
    v.y = fmaxf(v.y + bi.y, 0.f) * sc.y + sh.y;
    v.z = fmaxf(v.z + bi.z, 0.f) * sc.z + sh.z;
    v.w = fmaxf(v.w + bi.w, 0.f) * sc.w + sh.w;
    *reinterpret_cast<float4*>(&h[i4 * 4]) = v;
}

// ---------------- pooling (batch sorted: run-length accumulate) ------------
__global__ __launch_bounds__(256) void pool_kernel(const float* __restrict__ h,
                                                   const int* __restrict__ batch,
                                                   float* __restrict__ pooled)
{
    int c = threadIdx.x;
    int n0 = blockIdx.x * 128, n1 = min(NN, n0 + 128);
    if (n0 >= NN) return;
    float acc = 0.f;
    int cur = batch[n0];
    for (int n = n0; n < n1; n++) {
        int b = batch[n];
        if (b != cur) {
            atomicAdd(&pooled[cur * 256 + c], acc);
            acc = 0.f;
            cur = b;
        }
        acc += h[(size_t)n * 256 + c];
    }
    atomicAdd(&pooled[cur * 256 + c], acc);
}

__global__ void fc1_kernel(const float* __restrict__ pooled, const float* __restrict__ w,
                           const float* __restrict__ b, float* __restrict__ out)
{
    int gph = blockIdx.x;
    int j = threadIdx.x;
    float s = b[j];
    const float* p = pooled + gph * 256;
#pragma unroll 8
    for (int k = 0; k < 256; k++) s += p[k] * w[k * 64 + j];
    out[gph * 64 + j] = fmaxf(s, 0.f);
}

__global__ void fc2_kernel(const float* __restrict__ fc1o, const float* __restrict__ w,
                           const float* __restrict__ b, float* __restrict__ out)
{
    int gph = blockIdx.x * blockDim.x + threadIdx.x;
    if (gph >= GG) return;
    float s = b[0];
    const float* f = fc1o + gph * 64;
#pragma unroll
    for (int j = 0; j < 64; j++) s += f[j] * w[j];
    out[gph] = s;
}

// ---------------- launch ----------------
extern "C" void kernel_launch(void* const* d_in, const int* in_sizes, int n_in,
                              void* d_out, int out_size)
{
    const float* x = (const float*)d_in[0];
    const float* edge_attr = (const float*)d_in[1];
    const int* edge_index;
    const int* batch;
    int wi;
    if (in_sizes[2] == 2 * EE) {
        edge_index = (const int*)d_in[2];
        batch = (const int*)d_in[3];
        wi = 4;
    } else {
        edge_index = (const int*)d_in[n_in - 2];
        batch = (const int*)d_in[n_in - 1];
        wi = 2;
    }
    const float* dr1_w = (const float*)d_in[wi + 0];
    const float* dr1_b = (const float*)d_in[wi + 1];
    const float* dr2_w = (const float*)d_in[wi + 2];
    const float* dr2_b = (const float*)d_in[wi + 3];
    const float* c1_wl = (const float*)d_in[wi + 4];
    const float* c1_wr = (const float*)d_in[wi + 5];
    const float* c1_we = (const float*)d_in[wi + 6];
    const float* c1_att = (const float*)d_in[wi + 7];
    const float* c1_b = (const float*)d_in[wi + 8];
    const float* bn1_g = (const float*)d_in[wi + 9];
    const float* bn1_b = (const float*)d_in[wi + 10];
    const float* c2_wl = (const float*)d_in[wi + 11];
    const float* c2_wr = (const float*)d_in[wi + 12];
    const float* c2_we = (const float*)d_in[wi + 13];
    const float* c2_att = (const float*)d_in[wi + 14];
    const float* c2_b = (const float*)d_in[wi + 15];
    const float* bn2_g = (const float*)d_in[wi + 16];
    const float* bn2_b = (const float*)d_in[wi + 17];
    const float* fc1_w = (const float*)d_in[wi + 18];
    const float* fc1_b = (const float*)d_in[wi + 19];
    const float* fc2_w = (const float*)d_in[wi + 20];
    const float* fc2_b = (const float*)d_in[wi + 21];
    float* out = (float*)d_out;

    float *xl1, *xr1, *out1, *d256a, *xr2, *out2, *h64, *score;
    float *bnsum, *bnsq, *scalep, *shiftp, *pool, *fc1o;
    int *deg, *rowstart, *cursor, *esrc, *eid;
    cudaGetSymbolAddress((void**)&xl1, g_xl1);
    cudaGetSymbolAddress((void**)&xr1, g_xr1);
    cudaGetSymbolAddress((void**)&out1, g_out1);
    cudaGetSymbolAddress((void**)&d256a, g_d256a);
    cudaGetSymbolAddress((void**)&xr2, g_xr2);
    cudaGetSymbolAddress((void**)&out2, g_out2);
    cudaGetSymbolAddress((void**)&h64, g_h64);
    cudaGetSymbolAddress((void**)&score, g_score);
    cudaGetSymbolAddress((void**)&deg, g_deg);
    cudaGetSymbolAddress((void**)&rowstart, g_rowstart);
    cudaGetSymbolAddress((void**)&cursor, g_cursor);
    cudaGetSymbolAddress((void**)&esrc, g_esrc);
    cudaGetSymbolAddress((void**)&eid, g_eid);
    cudaGetSymbolAddress((void**)&bnsum, g_bnsum);
    cudaGetSymbolAddress((void**)&bnsq, g_bnsq);
    cudaGetSymbolAddress((void**)&scalep, g_scale);
    cudaGetSymbolAddress((void**)&shiftp, g_shift);
    cudaGetSymbolAddress((void**)&pool, g_pool);
    cudaGetSymbolAddress((void**)&fc1o, g_fc1o);

    dim3 blk256(256);
    const int GY = NP / 128;   // 157
    const int SMB = gemm_smem_bytes();

    cudaFuncSetAttribute(tf32_gemm<true, true>,
                         cudaFuncAttributeMaxDynamicSharedMemorySize, SMB);
    cudaFuncSetAttribute(tf32_gemm<false, true>,
                         cudaFuncAttributeMaxDynamicSharedMemorySize, SMB);
    cudaFuncSetAttribute(tf32_gemm<false, false>,
                         cudaFuncAttributeMaxDynamicSharedMemorySize, SMB);

    // CSR build (dst-sorted)
    cudaMemsetAsync(deg, 0, NN * sizeof(int), 0);
    hist_kernel<<<cdiv(EE, 256), blk256>>>(edge_index, deg);
    scan_kernel<<<1, 512>>>(deg, rowstart);
    cudaMemcpyAsync(cursor, rowstart, NN * sizeof(int), cudaMemcpyDeviceToDevice, 0);
    scatter_kernel<<<cdiv(EE, 256), blk256>>>(edge_index, cursor, esrc, eid);

    // node MLP (3xTF32 tensor cores, fp32-accurate, 2 CTAs/SM)
    tf32_gemm<true, true><<<dim3(4, GY), blk256, SMB>>>(
        x, dr1_w, dr1_b, d256a, NN, 256, 512);
    tf32_gemm<false, true><<<dim3(1, GY), blk256, SMB>>>(
        d256a, dr2_w, dr2_b, h64, NP, 64, 256);
    tf32_gemm<false, false><<<dim3(16, GY), blk256, SMB>>>(
        h64, c1_wl, nullptr, xl1, NP, 1024, 64);
    tf32_gemm<false, false><<<dim3(16, GY), blk256, SMB>>>(
        h64, c1_wr, nullptr, xr1, NP, 1024, 64);

    // conv1 edge phase
    gat_edge_kernel<1024, 8><<<740, blk256>>>(xl1, xr1, edge_attr, c1_we, c1_att,
                                              rowstart, esrc, eid, score, out1);

    // bn1
    cudaMemsetAsync(bnsum, 0, 1024 * sizeof(float), 0);
    cudaMemsetAsync(bnsq, 0, 1024 * sizeof(float), 0);
    bn_stats_kernel<1024><<<dim3(cdiv(NN, 128), 4), blk256>>>(out1, c1_b, bnsum, bnsq);
    bn_final_kernel<<<4, blk256>>>(bnsum, bnsq, bn1_g, bn1_b, scalep, shiftp, 1024);
    bn_apply_kernel<1024><<<cdiv(NN * 1024 / 4, 256), blk256>>>(out1, c1_b, scalep, shiftp);

    // conv2 projections
    tf32_gemm<false, false><<<dim3(4, GY), blk256, SMB>>>(
        out1, c2_wl, nullptr, d256a, NP, 256, 1024);
    tf32_gemm<false, false><<<dim3(4, GY), blk256, SMB>>>(
        out1, c2_wr, nullptr, xr2, NP, 256, 1024);

    // conv2 edge phase
    gat_edge_kernel<256, 6><<<1184, blk256>>>(d256a, xr2, edge_attr, c2_we, c2_att,
                                              rowstart, esrc, eid, score, out2);

    // bn2
    cudaMemsetAsync(bnsum, 0, 256 * sizeof(float), 0);
    cudaMemsetAsync(bnsq, 0, 256 * sizeof(float), 0);
    bn_stats_kernel<256><<<dim3(cdiv(NN, 128), 1), blk256>>>(out2, c2_b, bnsum, bnsq);
    bn_final_kernel<<<1, blk256>>>(bnsum, bnsq, bn2_g, bn2_b, scalep, shiftp, 256);
    bn_apply_kernel<256><<<cdiv(NN * 256 / 4, 256), blk256>>>(out2, c2_b, scalep, shiftp);

    // pool + head
    cudaMemsetAsync(pool, 0, GG * 256 * sizeof(float), 0);
    pool_kernel<<<cdiv(NN, 128), blk256>>>(out2, batch, pool);
    fc1_kernel<<<GG, 64>>>(pool, fc1_w, fc1_b, fc1o);
    fc2_kernel<<<1, 128>>>(fc1o, fc2_w, fc2_b, out);
    (void)out_size; (void)n_in; (void)in_sizes;
}

// round 11
// speedup vs baseline: 1.3299x; 1.2208x over previous
#include <cuda_runtime.h>
#include <math.h>

#define NN 20000
#define NP 20096          // 157 * 128 (padded rows for GEMM outputs)
#define EE 320000
#define GG 128

static inline int cdiv(int a, int b) { return (a + b - 1) / b; }

// ---------------- scratch ----------------
__device__ float g_xl1[NP * 1024];
__device__ float g_xr1[NP * 1024];
__device__ float g_out1[NP * 1024];
__device__ float g_d256a[NP * 256];
__device__ float g_xr2[NP * 256];
__device__ float g_out2[NN * 256];
__device__ float g_h64[NP * 64];
__device__ float g_score[EE * 4];
__device__ int   g_deg[NN];
__device__ int   g_rowstart[NN + 1];
__device__ int   g_cursor[NN];
__device__ int   g_esrc[EE];
__device__ int   g_eid[EE];
__device__ float g_bnsum[1024];
__device__ float g_bnsq[1024];
__device__ float g_scale[1024];
__device__ float g_shift[1024];
__device__ float g_pool[GG * 256];
__device__ float g_fc1o[GG * 64];

// ---------------- CSR build ----------------
__global__ void hist_kernel(const int* __restrict__ ei, int* __restrict__ deg)
{
    int e = blockIdx.x * blockDim.x + threadIdx.x;
    if (e < EE) atomicAdd(&deg[ei[EE + e]], 1);
}

__global__ __launch_bounds__(512) void scan_kernel(const int* __restrict__ deg,
                                                   int* __restrict__ rowstart)
{
    __shared__ int ps[512];
    int t = threadIdx.x;
    const int CH = (NN + 511) / 512;
    int s0 = t * CH, s1 = min(NN, s0 + CH);
    int s = 0;
    for (int i = s0; i < s1; i++) s += deg[i];
    ps[t] = s;
    __syncthreads();
    for (int off = 1; off < 512; off <<= 1) {
        int v = (t >= off) ? ps[t - off] : 0;
        __syncthreads();
        ps[t] += v;
        __syncthreads();
    }
    int run = (t == 0) ? 0 : ps[t - 1];
    for (int i = s0; i < s1; i++) { rowstart[i] = run; run += deg[i]; }
    if (t == 511) rowstart[NN] = run;
}

__global__ void scatter_kernel(const int* __restrict__ ei, int* __restrict__ cursor,
                               int* __restrict__ esrc, int* __restrict__ eid)
{
    int e = blockIdx.x * blockDim.x + threadIdx.x;
    if (e >= EE) return;
    int dst = ei[EE + e];
    int pos = atomicAdd(&cursor[dst], 1);
    esrc[pos] = ei[e];
    eid[pos] = e;
}

// ---------------- FFMA SGEMM v2: C = A[M,K] @ W[K,N] (+bias, relu) ------------
// BM=128, BN template (128 or 64), BK=16, 256 threads (16x16), TM=8, TN=BN/16.
// 64 FMA per 16 smem floats per k-step (TN=8) — fma-pipe bound by design.
template <int BN, bool RELU, bool HAS_BIAS>
__global__ __launch_bounds__(256) void sgemm_kernel(
    const float* __restrict__ A, const float* __restrict__ W,
    const float* __restrict__ bias, float* __restrict__ C,
    int Mld, int N, int K)
{
    constexpr int BM = 128, BK = 16;
    constexpr int TM = 8, TN = BN / 16;
    constexpr int W_ITERS = (BK * BN / 4) / 256;   // float4 loads of W per tile

    __shared__ float As[BK][BM + 4];   // transposed: As[k][m]
    __shared__ float Ws[BK][BN + 4];

    int tid = threadIdx.x;
    int tx = tid & 15;          // n dir: 16 * TN
    int ty = tid >> 4;          // m dir: 16 * TM
    int rowBase = blockIdx.y * BM;
    int colBase = blockIdx.x * BN;

    float acc[TM][TN];
#pragma unroll
    for (int i = 0; i < TM; i++)
#pragma unroll
        for (int j = 0; j < TN; j++) acc[i][j] = 0.f;

    for (int k0 = 0; k0 < K; k0 += BK) {
        // A tile: 128 rows x 16 k = 512 float4 (4 per row), 2 iters
#pragma unroll
        for (int it = 0; it < 2; it++) {
            int idx = tid + it * 256;
            int r = idx >> 2;
            int kc = (idx & 3) * 4;
            int gr = rowBase + r;
            float4 v = make_float4(0.f, 0.f, 0.f, 0.f);
            if (gr < Mld) v = *reinterpret_cast<const float4*>(&A[(size_t)gr * K + k0 + kc]);
            As[kc + 0][r] = v.x;
            As[kc + 1][r] = v.y;
            As[kc + 2][r] = v.z;
            As[kc + 3][r] = v.w;
        }
        // W tile: 16 rows x BN cols
#pragma unroll
        for (int it = 0; it < W_ITERS; it++) {
            int idx = tid + it * 256;
            int r = idx / (BN / 4);
            int c4 = idx % (BN / 4);
            *reinterpret_cast<float4*>(&Ws[r][c4 * 4]) =
                *reinterpret_cast<const float4*>(&W[(size_t)(k0 + r) * N + colBase + c4 * 4]);
        }
        __syncthreads();
#pragma unroll
        for (int k = 0; k < BK; k++) {
            float a[TM], b[TN];
            float4 a0 = *reinterpret_cast<const float4*>(&As[k][ty * TM]);
            float4 a1 = *reinterpret_cast<const float4*>(&As[k][ty * TM + 4]);
            a[0] = a0.x; a[1] = a0.y; a[2] = a0.z; a[3] = a0.w;
            a[4] = a1.x; a[5] = a1.y; a[6] = a1.z; a[7] = a1.w;
            float4 b0 = *reinterpret_cast<const float4*>(&Ws[k][tx * TN]);
            b[0] = b0.x; b[1] = b0.y; b[2] = b0.z; b[3] = b0.w;
            if (TN == 8) {
                float4 b1 = *reinterpret_cast<const float4*>(&Ws[k][tx * TN + 4]);
                b[4] = b1.x; b[5] = b1.y; b[6] = b1.z; b[7] = b1.w;
            }
#pragma unroll
            for (int i = 0; i < TM; i++)
#pragma unroll
                for (int j = 0; j < TN; j++) acc[i][j] = fmaf(a[i], b[j], acc[i][j]);
        }
        __syncthreads();
    }

#pragma unroll
    for (int i = 0; i < TM; i++) {
        int r = rowBase + ty * TM + i;
#pragma unroll
        for (int j4 = 0; j4 < TN / 4; j4++) {
            int ccol = colBase + tx * TN + j4 * 4;
            float4 v;
            v.x = acc[i][j4 * 4 + 0];
            v.y = acc[i][j4 * 4 + 1];
            v.z = acc[i][j4 * 4 + 2];
            v.w = acc[i][j4 * 4 + 3];
            if (HAS_BIAS) {
                v.x += bias[ccol + 0];
                v.y += bias[ccol + 1];
                v.z += bias[ccol + 2];
                v.w += bias[ccol + 3];
            }
            if (RELU) {
                v.x = fmaxf(v.x, 0.f); v.y = fmaxf(v.y, 0.f);
                v.z = fmaxf(v.z, 0.f); v.w = fmaxf(v.w, 0.f);
            }
            *reinterpret_cast<float4*>(&C[(size_t)r * N + ccol]) = v;
        }
    }
}

// ---------------- fused GATv2 edge phase (per-dst CSR, no atomics) ----------------
template <int CT, int HSHIFT>
__global__ __launch_bounds__(256) void gat_edge_kernel(
    const float* __restrict__ xl, const float* __restrict__ xr,
    const float* __restrict__ ea, const float* __restrict__ we,
    const float* __restrict__ att,
    const int* __restrict__ rowstart, const int* __restrict__ esrc,
    const int* __restrict__ eid,
    float* __restrict__ gscore_fb,
    float* __restrict__ out)
{
    constexpr int MAXDEG = 256;
    constexpr int CU = CT / 256;
    __shared__ float we_s[8 * CT];
    __shared__ float att_s[CT];
    __shared__ float xr_s[CT];
    __shared__ float sc_s[MAXDEG * 4];
    int tid = threadIdx.x, lane = tid & 31, wid = tid >> 5;
    for (int i = tid; i < 8 * CT; i += 256) we_s[i] = we[i];
    for (int i = tid; i < CT; i += 256) att_s[i] = att[i];
    __syncthreads();

    for (int node = blockIdx.x; node < NN; node += gridDim.x) {
        int rs = rowstart[node];
        int deg = rowstart[node + 1] - rs;
        if (deg == 0) {
#pragma unroll
            for (int u = 0; u < CU; u++) out[(size_t)node * CT + u * 256 + tid] = 0.f;
            continue;
        }
#pragma unroll
        for (int u = 0; u < CU; u++)
            xr_s[u * 256 + tid] = xr[(size_t)node * CT + u * 256 + tid];
        __syncthreads();
        float* sc = (deg <= MAXDEG) ? sc_s : (gscore_fb + (size_t)rs * 4);

        for (int j = wid; j < deg; j += 8) {
            int src = esrc[rs + j];
            int e = eid[rs + j];
            float eav[8];
#pragma unroll
            for (int k = 0; k < 8; k++) eav[k] = __ldg(&ea[(size_t)e * 8 + k]);
            const float* xls = xl + (size_t)src * CT;
            float acc[4] = {0.f, 0.f, 0.f, 0.f};
#pragma unroll
            for (int it = 0; it < CT / 32; it++) {
                int c = lane + 32 * it;
                const int h = (32 * it) >> HSHIFT;
                float eec = 0.f;
#pragma unroll
                for (int k = 0; k < 8; k++) eec = fmaf(eav[k], we_s[k * CT + c], eec);
                float m = xls[c] + xr_s[c] + eec;
                m = (m > 0.f) ? m : 0.2f * m;
                acc[h] = fmaf(m, att_s[c], acc[h]);
            }
#pragma unroll
            for (int h = 0; h < 4; h++) {
#pragma unroll
                for (int off = 16; off > 0; off >>= 1)
                    acc[h] += __shfl_xor_sync(0xffffffffu, acc[h], off);
            }
            if (lane == 0) {
                sc[j * 4 + 0] = acc[0];
                sc[j * 4 + 1] = acc[1];
                sc[j * 4 + 2] = acc[2];
                sc[j * 4 + 3] = acc[3];
            }
        }
        __syncthreads();

        if (wid < 4) {
            float mx = -1e30f;
            for (int j = lane; j < deg; j += 32) mx = fmaxf(mx, sc[j * 4 + wid]);
#pragma unroll
            for (int off = 16; off > 0; off >>= 1)
                mx = fmaxf(mx, __shfl_xor_sync(0xffffffffu, mx, off));
            float sum = 0.f;
            for (int j = lane; j < deg; j += 32) {
                float v = expf(sc[j * 4 + wid] - mx);
                sc[j * 4 + wid] = v;
                sum += v;
            }
#pragma unroll
            for (int off = 16; off > 0; off >>= 1)
                sum += __shfl_xor_sync(0xffffffffu, sum, off);
            float inv = 1.f / sum;
            for (int j = lane; j < deg; j += 32) sc[j * 4 + wid] *= inv;
        }
        __syncthreads();

        float racc[CU];
#pragma unroll
        for (int u = 0; u < CU; u++) racc[u] = 0.f;
        for (int j = 0; j < deg; j++) {
            int src = esrc[rs + j];
            const float* xls = xl + (size_t)src * CT;
#pragma unroll
            for (int u = 0; u < CU; u++) {
                int c = u * 256 + tid;
                float al = sc[j * 4 + (c >> HSHIFT)];
                racc[u] = fmaf(al, xls[c], racc[u]);
            }
        }
#pragma unroll
        for (int u = 0; u < CU; u++)
            out[(size_t)node * CT + u * 256 + tid] = racc[u];
        __syncthreads();
    }
}

// ---------------- BN (fused bias + relu) ----------------
template <int C>
__global__ void bn_stats_kernel(const float* __restrict__ h,
                                const float* __restrict__ bias,
                                float* __restrict__ sum, float* __restrict__ sq)
{
    int c = blockIdx.y * blockDim.x + threadIdx.x;
    int r0 = blockIdx.x * 128;
    int r1 = min(NN, r0 + 128);
    float b = bias[c];
    float s = 0.f, q = 0.f;
    for (int r = r0; r < r1; r++) {
        float v = h[(size_t)r * C + c] + b;
        v = fmaxf(v, 0.f);
        s += v;
        q += v * v;
    }
    atomicAdd(&sum[c], s);
    atomicAdd(&sq[c], q);
}

__global__ void bn_final_kernel(const float* __restrict__ sum, const float* __restrict__ sq,
                                const float* __restrict__ g, const float* __restrict__ b,
                                float* __restrict__ scale, float* __restrict__ shift, int C)
{
    int c = blockIdx.x * blockDim.x + threadIdx.x;
    if (c >= C) return;
    const float invN = 1.f / (float)NN;
    float mu = sum[c] * invN;
    float var = sq[c] * invN - mu * mu;
    var = fmaxf(var, 0.f);
    float rs = rsqrtf(var + 1e-5f);
    float sc = g[c] * rs;
    scale[c] = sc;
    shift[c] = b[c] - mu * sc;
}

template <int C>
__global__ void bn_apply_kernel(float* __restrict__ h, const float* __restrict__ bias,
                                const float* __restrict__ scale, const float* __restrict__ shift)
{
    size_t i4 = (size_t)blockIdx.x * blockDim.x + threadIdx.x;
    size_t total4 = (size_t)NN * C / 4;
    if (i4 >= total4) return;
    int c = (int)((i4 * 4) % C);
    float4 v = *reinterpret_cast<float4*>(&h[i4 * 4]);
    float4 bi = *reinterpret_cast<const float4*>(&bias[c]);
    float4 sc = *reinterpret_cast<const float4*>(&scale[c]);
    float4 sh = *reinterpret_cast<const float4*>(&shift[c]);
    v.x = fmaxf(v.x + bi.x, 0.f) * sc.x + sh.x;
    v.y = fmaxf(v.y + bi.y, 0.f) * sc.y + sh.y;
    v.z = fmaxf(v.z + bi.z, 0.f) * sc.z + sh.z;
    v.w = fmaxf(v.w + bi.w, 0.f) * sc.w + sh.w;
    *reinterpret_cast<float4*>(&h[i4 * 4]) = v;
}

// ---------------- pooling (batch sorted: run-length accumulate) ------------
__global__ __launch_bounds__(256) void pool_kernel(const float* __restrict__ h,
                                                   const int* __restrict__ batch,
                                                   float* __restrict__ pooled)
{
    int c = threadIdx.x;
    int n0 = blockIdx.x * 128, n1 = min(NN, n0 + 128);
    if (n0 >= NN) return;
    float acc = 0.f;
    int cur = batch[n0];
    for (int n = n0; n < n1; n++) {
        int b = batch[n];
        if (b != cur) {
            atomicAdd(&pooled[cur * 256 + c], acc);
            acc = 0.f;
            cur = b;
        }
        acc += h[(size_t)n * 256 + c];
    }
    atomicAdd(&pooled[cur * 256 + c], acc);
}

__global__ void fc1_kernel(const float* __restrict__ pooled, const float* __restrict__ w,
                           const float* __restrict__ b, float* __restrict__ out)
{
    int gph = blockIdx.x;
    int j = threadIdx.x;
    float s = b[j];
    const float* p = pooled + gph * 256;
#pragma unroll 8
    for (int k = 0; k < 256; k++) s += p[k] * w[k * 64 + j];
    out[gph * 64 + j] = fmaxf(s, 0.f);
}

__global__ void fc2_kernel(const float* __restrict__ fc1o, const float* __restrict__ w,
                           const float* __restrict__ b, float* __restrict__ out)
{
    int gph = blockIdx.x * blockDim.x + threadIdx.x;
    if (gph >= GG) return;
    float s = b[0];
    const float* f = fc1o + gph * 64;
#pragma unroll
    for (int j = 0; j < 64; j++) s += f[j] * w[j];
    out[gph] = s;
}

// ---------------- launch ----------------
extern "C" void kernel_launch(void* const* d_in, const int* in_sizes, int n_in,
                              void* d_out, int out_size)
{
    const float* x = (const float*)d_in[0];
    const float* edge_attr = (const float*)d_in[1];
    const int* edge_index;
    const int* batch;
    int wi;
    if (in_sizes[2] == 2 * EE) {
        edge_index = (const int*)d_in[2];
        batch = (const int*)d_in[3];
        wi = 4;
    } else {
        edge_index = (const int*)d_in[n_in - 2];
        batch = (const int*)d_in[n_in - 1];
        wi = 2;
    }
    const float* dr1_w = (const float*)d_in[wi + 0];
    const float* dr1_b = (const float*)d_in[wi + 1];
    const float* dr2_w = (const float*)d_in[wi + 2];
    const float* dr2_b = (const float*)d_in[wi + 3];
    const float* c1_wl = (const float*)d_in[wi + 4];
    const float* c1_wr = (const float*)d_in[wi + 5];
    const float* c1_we = (const float*)d_in[wi + 6];
    const float* c1_att = (const float*)d_in[wi + 7];
    const float* c1_b = (const float*)d_in[wi + 8];
    const float* bn1_g = (const float*)d_in[wi + 9];
    const float* bn1_b = (const float*)d_in[wi + 10];
    const float* c2_wl = (const float*)d_in[wi + 11];
    const float* c2_wr = (const float*)d_in[wi + 12];
    const float* c2_we = (const float*)d_in[wi + 13];
    const float* c2_att = (const float*)d_in[wi + 14];
    const float* c2_b = (const float*)d_in[wi + 15];
    const float* bn2_g = (const float*)d_in[wi + 16];
    const float* bn2_b = (const float*)d_in[wi + 17];
    const float* fc1_w = (const float*)d_in[wi + 18];
    const float* fc1_b = (const float*)d_in[wi + 19];
    const float* fc2_w = (const float*)d_in[wi + 20];
    const float* fc2_b = (const float*)d_in[wi + 21];
    float* out = (float*)d_out;

    float *xl1, *xr1, *out1, *d256a, *xr2, *out2, *h64, *score;
    float *bnsum, *bnsq, *scalep, *shiftp, *pool, *fc1o;
    int *deg, *rowstart, *cursor, *esrc, *eid;
    cudaGetSymbolAddress((void**)&xl1, g_xl1);
    cudaGetSymbolAddress((void**)&xr1, g_xr1);
    cudaGetSymbolAddress((void**)&out1, g_out1);
    cudaGetSymbolAddress((void**)&d256a, g_d256a);
    cudaGetSymbolAddress((void**)&xr2, g_xr2);
    cudaGetSymbolAddress((void**)&out2, g_out2);
    cudaGetSymbolAddress((void**)&h64, g_h64);
    cudaGetSymbolAddress((void**)&score, g_score);
    cudaGetSymbolAddress((void**)&deg, g_deg);
    cudaGetSymbolAddress((void**)&rowstart, g_rowstart);
    cudaGetSymbolAddress((void**)&cursor, g_cursor);
    cudaGetSymbolAddress((void**)&esrc, g_esrc);
    cudaGetSymbolAddress((void**)&eid, g_eid);
    cudaGetSymbolAddress((void**)&bnsum, g_bnsum);
    cudaGetSymbolAddress((void**)&bnsq, g_bnsq);
    cudaGetSymbolAddress((void**)&scalep, g_scale);
    cudaGetSymbolAddress((void**)&shiftp, g_shift);
    cudaGetSymbolAddress((void**)&pool, g_pool);
    cudaGetSymbolAddress((void**)&fc1o, g_fc1o);

    dim3 blk256(256);
    const int GY = NP / 128;   // 157

    // CSR build (dst-sorted)
    cudaMemsetAsync(deg, 0, NN * sizeof(int), 0);
    hist_kernel<<<cdiv(EE, 256), blk256>>>(edge_index, deg);
    scan_kernel<<<1, 512>>>(deg, rowstart);
    cudaMemcpyAsync(cursor, rowstart, NN * sizeof(int), cudaMemcpyDeviceToDevice, 0);
    scatter_kernel<<<cdiv(EE, 256), blk256>>>(edge_index, cursor, esrc, eid);

    // node MLP (FFMA, high arithmetic intensity)
    sgemm_kernel<128, true, true><<<dim3(2, GY), blk256>>>(
        x, dr1_w, dr1_b, d256a, NN, 256, 512);
    sgemm_kernel<64, false, true><<<dim3(1, GY), blk256>>>(
        d256a, dr2_w, dr2_b, h64, NP, 64, 256);
    sgemm_kernel<128, false, false><<<dim3(8, GY), blk256>>>(
        h64, c1_wl, nullptr, xl1, NP, 1024, 64);
    sgemm_kernel<128, false, false><<<dim3(8, GY), blk256>>>(
        h64, c1_wr, nullptr, xr1, NP, 1024, 64);

    // conv1 edge phase
    gat_edge_kernel<1024, 8><<<740, blk256>>>(xl1, xr1, edge_attr, c1_we, c1_att,
                                              rowstart, esrc, eid, score, out1);

    // bn1
    cudaMemsetAsync(bnsum, 0, 1024 * sizeof(float), 0);
    cudaMemsetAsync(bnsq, 0, 1024 * sizeof(float), 0);
    bn_stats_kernel<1024><<<dim3(cdiv(NN, 128), 4), blk256>>>(out1, c1_b, bnsum, bnsq);
    bn_final_kernel<<<4, blk256>>>(bnsum, bnsq, bn1_g, bn1_b, scalep, shiftp, 1024);
    bn_apply_kernel<1024><<<cdiv(NN * 1024 / 4, 256), blk256>>>(out1, c1_b, scalep, shiftp);

    // conv2 projections
    sgemm_kernel<128, false, false><<<dim3(2, GY), blk256>>>(
        out1, c2_wl, nullptr, d256a, NP, 256, 1024);
    sgemm_kernel<128, false, false><<<dim3(2, GY), blk256>>>(
        out1, c2_wr, nullptr, xr2, NP, 256, 1024);

    // conv2 edge phase
    gat_edge_kernel<256, 6><<<1184, blk256>>>(d256a, xr2, edge_attr, c2_we, c2_att,
                                              rowstart, esrc, eid, score, out2);

    // bn2
    cudaMemsetAsync(bnsum, 0, 256 * sizeof(float), 0);
    cudaMemsetAsync(bnsq, 0, 256 * sizeof(float), 0);
    bn_stats_kernel<256><<<dim3(cdiv(NN, 128), 1), blk256>>>(out2, c2_b, bnsum, bnsq);
    bn_final_kernel<<<1, blk256>>>(bnsum, bnsq, bn2_g, bn2_b, scalep, shiftp, 256);
    bn_apply_kernel<256><<<cdiv(NN * 256 / 4, 256), blk256>>>(out2, c2_b, scalep, shiftp);

    // pool + head
    cudaMemsetAsync(pool, 0, GG * 256 * sizeof(float), 0);
    pool_kernel<<<cdiv(NN, 128), blk256>>>(out2, batch, pool);
    fc1_kernel<<<GG, 64>>>(pool, fc1_w, fc1_b, fc1o);
    fc2_kernel<<<1, 128>>>(fc1o, fc2_w, fc2_b, out);
    (void)out_size; (void)n_in; (void)in_sizes;
}